// round 1
// baseline (speedup 1.0000x reference)
#include <cuda_runtime.h>
#include <math.h>

// ---------------------------------------------------------------------------
// QFCModel: AvgPool(6) top-row blocks -> 4-qubit circuit (closed form)
//           -> cumulative Z products -> BatchNorm1d(4) training mode.
//
// out[b,0] = z0 ; out[b,1] = z0*z1 ; out[b,2] = z0*z1*z2 ; out[b,3] = z0*z1*z2*z3
// z_i = cos(lam_i)*cos(th_i) + sin(lam_i)*sin(phi_i)*sin(th_i)
//   th_i = mean of x[b,0, 0:6, 6i:6i+6]   (first 144 floats of each image)
//   phi_i = params[i,0], lam_i = params[i,1]
// ---------------------------------------------------------------------------

#define B_TOTAL 65536
#define NB      1024          // blocks in kernel A
#define IPB     64            // images per block (NB*IPB == B_TOTAL)
#define THREADS 256
#define SROW    148           // padded smem row (floats): 148%32==20 -> no conflicts

__device__ float g_part[NB * 8];   // per-block [sum0..3, sumsq0..3]
__device__ float g_sb[8];          // scale[4], bias[4]

__global__ __launch_bounds__(THREADS)
void qfc_kernelA(const float* __restrict__ x,
                 const float* __restrict__ pr,
                 float* __restrict__ out)
{
    __shared__ float sd[IPB][SROW];
    __shared__ float sz[IPB][4];
    __shared__ float sred[16];

    const int tid = threadIdx.x;
    const long base = (long)blockIdx.x * IPB;

    // -------- Phase 1: coalesced staged load of 64 images x 144 floats ------
    // image = 576 floats = 144 float4; we need the first 36 float4 of each.
    const float4* __restrict__ x4 = (const float4*)x;
#pragma unroll
    for (int it = 0; it < (IPB * 36) / THREADS; it++) {
        unsigned i = tid + it * THREADS;        // 0 .. 2303
        unsigned img = i / 36u;
        unsigned p   = i - img * 36u;           // float4 index within 144-float chunk
        float4 v = __ldg(&x4[(base + img) * 144 + p]);
        *(float4*)&sd[img][p * 4] = v;
    }
    __syncthreads();

    // -------- Phase 2: one thread per (image, column-group) -----------------
    {
        const int img = tid >> 2;
        const int g   = tid & 3;
        const float* row = &sd[img][g * 6];
        float s = 0.f;
#pragma unroll
        for (int r = 0; r < 6; r++)
#pragma unroll
            for (int c = 0; c < 6; c++)
                s += row[r * 24 + c];
        const float theta = s * (1.f / 36.f);
        const float phi = __ldg(&pr[g * 2 + 0]);
        const float lam = __ldg(&pr[g * 2 + 1]);
        float st, ct;
        __sincosf(theta, &st, &ct);
        const float z = cosf(lam) * ct + sinf(lam) * sinf(phi) * st;
        sz[img][g] = z;
    }
    __syncthreads();

    // -------- Phase 3: products, write out, deterministic block reduction ---
    float acc[8];
    if (tid < IPB) {
        float4 zz = *(float4*)&sz[tid][0];
        float o0 = zz.x;
        float o1 = o0 * zz.y;
        float o2 = o1 * zz.z;
        float o3 = o2 * zz.w;
        ((float4*)out)[base + tid] = make_float4(o0, o1, o2, o3);
        acc[0] = o0; acc[1] = o1; acc[2] = o2; acc[3] = o3;
        acc[4] = o0 * o0; acc[5] = o1 * o1; acc[6] = o2 * o2; acc[7] = o3 * o3;

        // warps 0 and 1 are fully covered by tid<64
#pragma unroll
        for (int k = 0; k < 8; k++) {
#pragma unroll
            for (int off = 16; off; off >>= 1)
                acc[k] += __shfl_down_sync(0xffffffffu, acc[k], off);
        }
        if ((tid & 31) == 0) {
#pragma unroll
            for (int k = 0; k < 8; k++)
                sred[(tid >> 5) * 8 + k] = acc[k];
        }
    }
    __syncthreads();
    if (tid < 8)
        g_part[blockIdx.x * 8 + tid] = sred[tid] + sred[8 + tid];
}

// -------- Kernel B: finalize batch stats in double (1 block) ----------------
__global__ __launch_bounds__(256)
void qfc_kernelB(const float* __restrict__ gamma, const float* __restrict__ beta)
{
    const int tid  = threadIdx.x;       // 256 threads: 8 channels x 32 lanes
    const int ch   = tid >> 5;
    const int lane = tid & 31;
    double a = 0.0;
    for (int b = lane; b < NB; b += 32)
        a += (double)g_part[b * 8 + ch];
#pragma unroll
    for (int off = 16; off; off >>= 1)
        a += __shfl_down_sync(0xffffffffu, a, off);

    __shared__ double sums[8];
    if (lane == 0) sums[ch] = a;
    __syncthreads();
    if (tid < 4) {
        const double mean = sums[tid]     * (1.0 / (double)B_TOTAL);
        const double ex2  = sums[tid + 4] * (1.0 / (double)B_TOTAL);
        const double var  = ex2 - mean * mean;
        const float inv   = (float)(1.0 / sqrt(var + 1e-5));
        const float sc    = __ldg(&gamma[tid]) * inv;
        g_sb[tid]     = sc;
        g_sb[4 + tid] = __ldg(&beta[tid]) - (float)mean * sc;
    }
}

// -------- Kernel C: in-place normalization (65536 float4) -------------------
__global__ __launch_bounds__(256)
void qfc_kernelC(float* __restrict__ out)
{
    const int i = blockIdx.x * blockDim.x + threadIdx.x;   // 65536 threads
    float4 v = ((float4*)out)[i];
    v.x = v.x * g_sb[0] + g_sb[4];
    v.y = v.y * g_sb[1] + g_sb[5];
    v.z = v.z * g_sb[2] + g_sb[6];
    v.w = v.w * g_sb[3] + g_sb[7];
    ((float4*)out)[i] = v;
}

extern "C" void kernel_launch(void* const* d_in, const int* in_sizes, int n_in,
                              void* d_out, int out_size)
{
    const float* x      = (const float*)d_in[0];   // [65536,1,24,24]
    const float* params = (const float*)d_in[1];   // [4,2]
    const float* gamma  = (const float*)d_in[2];   // [4]
    const float* beta   = (const float*)d_in[3];   // [4]
    float* out = (float*)d_out;                    // [65536,4]

    qfc_kernelA<<<NB, THREADS>>>(x, params, out);
    qfc_kernelB<<<1, 256>>>(gamma, beta);
    qfc_kernelC<<<B_TOTAL / 256, 256>>>(out);
}

// round 3
// speedup vs baseline: 1.0865x; 1.0865x over previous
#include <cuda_runtime.h>
#include <cstdint>
#include <math.h>

// ---------------------------------------------------------------------------
// QFCModel closed form:
//   theta_i = mean of x[b,0, 0:6, 6i:6i+6]  (first 144 floats of each image)
//   z_i = cos(lam_i)*cos(theta_i) + sin(lam_i)*sin(phi_i)*sin(theta_i)
//   out[b] = [z0, z0 z1, z0 z1 z2, z0 z1 z2 z3], then BatchNorm1d (batch stats)
// ---------------------------------------------------------------------------

#define B_TOTAL 65536
#define IPB     32                          // images per tile
#define TPB     2                           // tiles per block (pipelined)
#define NB      (B_TOTAL / (IPB * TPB))     // 1024 blocks in kernel A
#define THREADS 256
#define SROW    148                         // padded smem row (floats), 16B-aligned rows
#define NBC     128                         // blocks in fused BN kernel

__device__ float g_part[NB * 8];            // per-block [sum0..3, sumsq0..3]

__device__ __forceinline__ void cp16(unsigned int saddr, const float4* gptr) {
    asm volatile("cp.async.cg.shared.global [%0], [%1], 16;" :: "r"(saddr), "l"(gptr));
}

__global__ __launch_bounds__(THREADS)
void qfc_kernelA(const float* __restrict__ x,
                 const float* __restrict__ pr,
                 float* __restrict__ out)
{
    __shared__ __align__(16) float sd[TPB][IPB][SROW];
    __shared__ float sz[IPB][4];

    const int tid = threadIdx.x;
    const float4* __restrict__ x4 = (const float4*)x;
    const long t0 = (long)blockIdx.x * TPB;

    // ---- Prologue: commit BOTH tiles' loads before any compute -------------
    // per tile: 32 images x 36 float4 = 1152 cp.asyncs, ~4.5 per thread
#pragma unroll
    for (int s = 0; s < TPB; s++) {
        const long ib = (t0 + s) * IPB;
#pragma unroll
        for (int it = 0; it < 5; it++) {
            int i = tid + it * THREADS;
            if (i < IPB * 36) {
                int img = i / 36;
                int p   = i - img * 36;
                unsigned int sa = (unsigned int)__cvta_generic_to_shared(&sd[s][img][p * 4]);
                cp16(sa, &x4[(ib + img) * 144 + p]);
            }
        }
        asm volatile("cp.async.commit_group;");
    }

    // per-thread group constants (g = tid & 3)
    const int g = tid & 3;
    const float phi  = pr[g * 2 + 0];
    const float lam  = pr[g * 2 + 1];
    const float clam = __cosf(lam);
    const float k2   = __sinf(lam) * __sinf(phi);

    float acc[8];
#pragma unroll
    for (int k = 0; k < 8; k++) acc[k] = 0.f;

#pragma unroll
    for (int s = 0; s < TPB; s++) {
        if (s == 0) asm volatile("cp.async.wait_group 1;");
        else        asm volatile("cp.async.wait_group 0;");
        __syncthreads();

        // pooling + single-qubit closed form: 128 threads = 32 images x 4 groups
        if (tid < IPB * 4) {
            const int img = tid >> 2;
            const float* row = &sd[s][img][g * 6];
            float a0 = 0.f, a1 = 0.f, a2 = 0.f, a3 = 0.f;
#pragma unroll
            for (int r = 0; r < 6; r++) {
                a0 += row[r * 24 + 0];
                a1 += row[r * 24 + 1];
                a2 += row[r * 24 + 2];
                a3 += row[r * 24 + 3];
                a0 += row[r * 24 + 4];
                a1 += row[r * 24 + 5];
            }
            const float theta = ((a0 + a1) + (a2 + a3)) * (1.f / 36.f);
            float st, ct;
            __sincosf(theta, &st, &ct);
            sz[img][g] = clam * ct + k2 * st;
        }
        __syncthreads();

        // cumulative products + output write + partial-stat accumulation
        if (tid < IPB) {
            float4 zz = *(float4*)&sz[tid][0];
            float o0 = zz.x;
            float o1 = o0 * zz.y;
            float o2 = o1 * zz.z;
            float o3 = o2 * zz.w;
            ((float4*)out)[(t0 + s) * IPB + tid] = make_float4(o0, o1, o2, o3);
            acc[0] += o0;      acc[1] += o1;      acc[2] += o2;      acc[3] += o3;
            acc[4] += o0 * o0; acc[5] += o1 * o1; acc[6] += o2 * o2; acc[7] += o3 * o3;
        }
        __syncthreads();   // sz reused next stage
    }

    // deterministic warp reduction (warp 0 holds all partials)
    if (tid < 32) {
#pragma unroll
        for (int k = 0; k < 8; k++) {
#pragma unroll
            for (int off = 16; off; off >>= 1)
                acc[k] += __shfl_down_sync(0xffffffffu, acc[k], off);
        }
        if (tid == 0) {
#pragma unroll
            for (int k = 0; k < 8; k++)
                g_part[blockIdx.x * 8 + k] = acc[k];
        }
    }
}

// ---- Fused BatchNorm finalize + normalize (stats computed redundantly) -----
__global__ __launch_bounds__(256)
void qfc_kernelBC(const float* __restrict__ gamma,
                  const float* __restrict__ beta,
                  float* __restrict__ out)
{
    __shared__ double sums[8];
    __shared__ float sb[8];

    const int tid  = threadIdx.x;       // 8 channels x 32 lanes
    const int ch   = tid >> 5;
    const int lane = tid & 31;

    double a = 0.0;
    for (int b = lane; b < NB; b += 32)
        a += (double)g_part[b * 8 + ch];
#pragma unroll
    for (int off = 16; off; off >>= 1)
        a += __shfl_down_sync(0xffffffffu, a, off);
    if (lane == 0) sums[ch] = a;
    __syncthreads();

    if (tid < 4) {
        const double mean = sums[tid]     * (1.0 / (double)B_TOTAL);
        const double ex2  = sums[tid + 4] * (1.0 / (double)B_TOTAL);
        const double var  = ex2 - mean * mean;
        const float inv   = (float)(1.0 / sqrt(var + 1e-5));
        const float sc    = gamma[tid] * inv;
        sb[tid]     = sc;
        sb[4 + tid] = beta[tid] - (float)mean * sc;
    }
    __syncthreads();

    // normalize: 65536 float4 total / 128 blocks = 512 per block, 2 per thread
    float4* o4 = (float4*)out;
    int i = blockIdx.x * 512 + tid;
#pragma unroll
    for (int rep = 0; rep < 2; rep++, i += 256) {
        float4 v = o4[i];
        v.x = v.x * sb[0] + sb[4];
        v.y = v.y * sb[1] + sb[5];
        v.z = v.z * sb[2] + sb[6];
        v.w = v.w * sb[3] + sb[7];
        o4[i] = v;
    }
}

extern "C" void kernel_launch(void* const* d_in, const int* in_sizes, int n_in,
                              void* d_out, int out_size)
{
    const float* x      = (const float*)d_in[0];   // [65536,1,24,24]
    const float* params = (const float*)d_in[1];   // [4,2]
    const float* gamma  = (const float*)d_in[2];   // [4]
    const float* beta   = (const float*)d_in[3];   // [4]
    float* out = (float*)d_out;                    // [65536,4]

    qfc_kernelA<<<NB, THREADS>>>(x, params, out);
    qfc_kernelBC<<<NBC, 256>>>(gamma, beta, out);
}

// round 4
// speedup vs baseline: 1.1123x; 1.0238x over previous
#include <cuda_runtime.h>
#include <cstdint>
#include <math.h>

// ---------------------------------------------------------------------------
// QFCModel closed form:
//   theta_i = mean of x[b,0, 0:6, 6i:6i+6]  (first 144 floats of each image)
//   z_i = cos(lam_i)*cos(theta_i) + sin(lam_i)*sin(phi_i)*sin(theta_i)
//   out[b] = [z0, z0 z1, z0 z1 z2, z0 z1 z2 z3], then BatchNorm1d (batch stats)
// ---------------------------------------------------------------------------

#define B_TOTAL 65536
#define IPB     32                          // images per tile
#define TPB     2                           // tiles per block (pipelined)
#define NB      (B_TOTAL / (IPB * TPB))     // 1024 blocks in kernel A
#define THREADS 256
#define SROW    148                         // padded smem row (floats), 16B-aligned rows
#define NBC     128                         // blocks in fused BN kernel

__device__ __align__(16) float g_part[NB * 8];  // per-block [sum0..3, sumsq0..3]

__device__ __forceinline__ void cp16(unsigned int saddr, const float4* gptr) {
    asm volatile("cp.async.cg.shared.global [%0], [%1], 16;" :: "r"(saddr), "l"(gptr));
}

__global__ __launch_bounds__(THREADS)
void qfc_kernelA(const float* __restrict__ x,
                 const float* __restrict__ pr,
                 float* __restrict__ out)
{
    __shared__ __align__(16) float sd[TPB][IPB][SROW];
    __shared__ float sz[IPB][4];

    const int tid = threadIdx.x;
    const float4* __restrict__ x4 = (const float4*)x;
    const long t0 = (long)blockIdx.x * TPB;

    // ---- Prologue: commit BOTH tiles' loads before any compute -------------
#pragma unroll
    for (int s = 0; s < TPB; s++) {
        const long ib = (t0 + s) * IPB;
#pragma unroll
        for (int it = 0; it < 5; it++) {
            int i = tid + it * THREADS;
            if (i < IPB * 36) {
                int img = i / 36;
                int p   = i - img * 36;
                unsigned int sa = (unsigned int)__cvta_generic_to_shared(&sd[s][img][p * 4]);
                cp16(sa, &x4[(ib + img) * 144 + p]);
            }
        }
        asm volatile("cp.async.commit_group;");
    }

    const int g = tid & 3;
    const float phi  = pr[g * 2 + 0];
    const float lam  = pr[g * 2 + 1];
    const float clam = __cosf(lam);
    const float k2   = __sinf(lam) * __sinf(phi);

    float acc[8];
#pragma unroll
    for (int k = 0; k < 8; k++) acc[k] = 0.f;

#pragma unroll
    for (int s = 0; s < TPB; s++) {
        if (s == 0) asm volatile("cp.async.wait_group 1;");
        else        asm volatile("cp.async.wait_group 0;");
        __syncthreads();

        // pooling + single-qubit closed form: 128 threads = 32 images x 4 groups
        if (tid < IPB * 4) {
            const int img = tid >> 2;
            const float* row = &sd[s][img][g * 6];
            float a0 = 0.f, a1 = 0.f, a2 = 0.f, a3 = 0.f;
#pragma unroll
            for (int r = 0; r < 6; r++) {
                a0 += row[r * 24 + 0];
                a1 += row[r * 24 + 1];
                a2 += row[r * 24 + 2];
                a3 += row[r * 24 + 3];
                a0 += row[r * 24 + 4];
                a1 += row[r * 24 + 5];
            }
            const float theta = ((a0 + a1) + (a2 + a3)) * (1.f / 36.f);
            float st, ct;
            __sincosf(theta, &st, &ct);
            sz[img][g] = clam * ct + k2 * st;
        }
        __syncthreads();

        if (tid < IPB) {
            float4 zz = *(float4*)&sz[tid][0];
            float o0 = zz.x;
            float o1 = o0 * zz.y;
            float o2 = o1 * zz.z;
            float o3 = o2 * zz.w;
            ((float4*)out)[(t0 + s) * IPB + tid] = make_float4(o0, o1, o2, o3);
            acc[0] += o0;      acc[1] += o1;      acc[2] += o2;      acc[3] += o3;
            acc[4] += o0 * o0; acc[5] += o1 * o1; acc[6] += o2 * o2; acc[7] += o3 * o3;
        }
        __syncthreads();
    }

    // deterministic warp reduction (warp 0 holds all partials)
    if (tid < 32) {
#pragma unroll
        for (int k = 0; k < 8; k++) {
#pragma unroll
            for (int off = 16; off; off >>= 1)
                acc[k] += __shfl_down_sync(0xffffffffu, acc[k], off);
        }
        if (tid == 0) {
            *(float4*)&g_part[blockIdx.x * 8]     = make_float4(acc[0], acc[1], acc[2], acc[3]);
            *(float4*)&g_part[blockIdx.x * 8 + 4] = make_float4(acc[4], acc[5], acc[6], acc[7]);
        }
    }
}

// ---- Fused BatchNorm finalize + normalize (fp32 coalesced reduction) -------
__global__ __launch_bounds__(256)
void qfc_kernelBC(const float* __restrict__ gamma,
                  const float* __restrict__ beta,
                  float* __restrict__ out)
{
    __shared__ float swarp[8][8];   // [warp][sum0..3, sq0..3]
    __shared__ float sb[8];

    const int tid  = threadIdx.x;
    const int wrp  = tid >> 5;
    const int lane = tid & 31;

    // coalesced float4 accumulation over 1024 partial records (4 iters/thread)
    const float4* __restrict__ p4 = (const float4*)g_part;   // 2048 float4
    float4 as = make_float4(0.f, 0.f, 0.f, 0.f);
    float4 aq = make_float4(0.f, 0.f, 0.f, 0.f);
#pragma unroll
    for (int it = 0; it < NB / 256; it++) {
        int j = tid + it * 256;
        float4 s = p4[j * 2];
        float4 q = p4[j * 2 + 1];
        as.x += s.x; as.y += s.y; as.z += s.z; as.w += s.w;
        aq.x += q.x; aq.y += q.y; aq.z += q.z; aq.w += q.w;
    }
    float r[8] = {as.x, as.y, as.z, as.w, aq.x, aq.y, aq.z, aq.w};
#pragma unroll
    for (int k = 0; k < 8; k++) {
#pragma unroll
        for (int off = 16; off; off >>= 1)
            r[k] += __shfl_down_sync(0xffffffffu, r[k], off);
    }
    if (lane == 0) {
#pragma unroll
        for (int k = 0; k < 8; k++) swarp[wrp][k] = r[k];
    }
    __syncthreads();

    if (tid < 4) {
        float s = 0.f, q = 0.f;
#pragma unroll
        for (int w = 0; w < 8; w++) { s += swarp[w][tid]; q += swarp[w][4 + tid]; }
        const double mean = (double)s * (1.0 / (double)B_TOTAL);
        const double ex2  = (double)q * (1.0 / (double)B_TOTAL);
        const double var  = ex2 - mean * mean;
        const float inv   = (float)(1.0 / sqrt(var + 1e-5));
        const float sc    = gamma[tid] * inv;
        sb[tid]     = sc;
        sb[4 + tid] = beta[tid] - (float)mean * sc;
    }
    __syncthreads();

    const float4 scv = *(const float4*)&sb[0];
    const float4 biv = *(const float4*)&sb[4];

    // normalize: 65536 float4 total / 128 blocks = 512 per block, 2 per thread
    float4* o4 = (float4*)out;
    int i = blockIdx.x * 512 + tid;
#pragma unroll
    for (int rep = 0; rep < 2; rep++, i += 256) {
        float4 v = o4[i];
        v.x = v.x * scv.x + biv.x;
        v.y = v.y * scv.y + biv.y;
        v.z = v.z * scv.z + biv.z;
        v.w = v.w * scv.w + biv.w;
        o4[i] = v;
    }
}

extern "C" void kernel_launch(void* const* d_in, const int* in_sizes, int n_in,
                              void* d_out, int out_size)
{
    const float* x      = (const float*)d_in[0];   // [65536,1,24,24]
    const float* params = (const float*)d_in[1];   // [4,2]
    const float* gamma  = (const float*)d_in[2];   // [4]
    const float* beta   = (const float*)d_in[3];   // [4]
    float* out = (float*)d_out;                    // [65536,4]

    qfc_kernelA<<<NB, THREADS>>>(x, params, out);
    qfc_kernelBC<<<NBC, 256>>>(gamma, beta, out);
}

// round 5
// speedup vs baseline: 1.1470x; 1.0312x over previous
#include <cuda_runtime.h>
#include <cstdint>
#include <math.h>

// ---------------------------------------------------------------------------
// QFCModel closed form:
//   theta_i = mean of x[b,0, 0:6, 6i:6i+6]  (first 144 floats of each image)
//   z_i = cos(lam_i)*cos(theta_i) + sin(lam_i)*sin(phi_i)*sin(theta_i)
//   out[b] = [z0, z0 z1, z0 z1 z2, z0 z1 z2 z3], then BatchNorm1d (batch stats)
// ---------------------------------------------------------------------------

#define B_TOTAL 65536
#define IPB     32                      // images per block (kernel A)
#define NB      (B_TOTAL / IPB)         // 2048 blocks in kernel A
#define THREADS 256
#define SROW    148                     // padded smem row (floats)
#define NBC     128                     // blocks in fused BN kernel

__device__ __align__(16) float g_part[NB * 8];  // per-block [sum0..3, sumsq0..3]

__device__ __forceinline__ void cp16(unsigned int saddr, const float4* gptr) {
    asm volatile("cp.async.cg.shared.global [%0], [%1], 16;" :: "r"(saddr), "l"(gptr));
}

__global__ __launch_bounds__(THREADS)
void qfc_kernelA(const float* __restrict__ x,
                 const float* __restrict__ pr,
                 float* __restrict__ out)
{
    __shared__ __align__(16) float sd[IPB][SROW];
    __shared__ float sz[IPB][4];

    const int tid = threadIdx.x;
    const float4* __restrict__ x4 = (const float4*)x;
    const long ib = (long)blockIdx.x * IPB;

    // ---- stage 32 images x 144 floats via cp.async (1152 float4) -----------
#pragma unroll
    for (int it = 0; it < 5; it++) {
        int i = tid + it * THREADS;
        if (i < IPB * 36) {
            int img = i / 36;
            int p   = i - img * 36;
            unsigned int sa = (unsigned int)__cvta_generic_to_shared(&sd[img][p * 4]);
            cp16(sa, &x4[(ib + img) * 144 + p]);
        }
    }
    asm volatile("cp.async.commit_group;");

    const int g = tid & 3;
    const float phi  = pr[g * 2 + 0];
    const float lam  = pr[g * 2 + 1];
    const float clam = __cosf(lam);
    const float k2   = __sinf(lam) * __sinf(phi);

    asm volatile("cp.async.wait_group 0;");
    __syncthreads();

    // pooling + single-qubit closed form: 128 threads = 32 images x 4 groups
    if (tid < IPB * 4) {
        const int img = tid >> 2;
        const float* row = &sd[img][g * 6];
        float a0 = 0.f, a1 = 0.f, a2 = 0.f, a3 = 0.f;
#pragma unroll
        for (int r = 0; r < 6; r++) {
            a0 += row[r * 24 + 0];
            a1 += row[r * 24 + 1];
            a2 += row[r * 24 + 2];
            a3 += row[r * 24 + 3];
            a0 += row[r * 24 + 4];
            a1 += row[r * 24 + 5];
        }
        const float theta = ((a0 + a1) + (a2 + a3)) * (1.f / 36.f);
        float st, ct;
        __sincosf(theta, &st, &ct);
        sz[img][g] = clam * ct + k2 * st;
    }
    __syncthreads();

    // products + output write + deterministic warp-0 reduction
    if (tid < 32) {
        float4 zz = *(float4*)&sz[tid][0];
        float o0 = zz.x;
        float o1 = o0 * zz.y;
        float o2 = o1 * zz.z;
        float o3 = o2 * zz.w;
        ((float4*)out)[ib + tid] = make_float4(o0, o1, o2, o3);

        float acc[8] = {o0, o1, o2, o3, o0 * o0, o1 * o1, o2 * o2, o3 * o3};
#pragma unroll
        for (int k = 0; k < 8; k++) {
#pragma unroll
            for (int off = 16; off; off >>= 1)
                acc[k] += __shfl_down_sync(0xffffffffu, acc[k], off);
        }
        if (tid == 0) {
            *(float4*)&g_part[blockIdx.x * 8]     = make_float4(acc[0], acc[1], acc[2], acc[3]);
            *(float4*)&g_part[blockIdx.x * 8 + 4] = make_float4(acc[4], acc[5], acc[6], acc[7]);
        }
    }
}

// ---- Fused BatchNorm finalize + normalize — ALL fp32, no fp64 anywhere -----
__global__ __launch_bounds__(256)
void qfc_kernelBC(const float* __restrict__ gamma,
                  const float* __restrict__ beta,
                  float* __restrict__ out)
{
    __shared__ float swarp[8][8];   // [warp][sum0..3, sq0..3]
    __shared__ float sb[8];

    const int tid  = threadIdx.x;
    const int wrp  = tid >> 5;
    const int lane = tid & 31;

    // coalesced float4 accumulation over 2048 partial records (8 iters/thread)
    const float4* __restrict__ p4 = (const float4*)g_part;   // 4096 float4
    float4 as = make_float4(0.f, 0.f, 0.f, 0.f);
    float4 aq = make_float4(0.f, 0.f, 0.f, 0.f);
#pragma unroll
    for (int it = 0; it < NB / 256; it++) {
        int j = tid + it * 256;
        float4 s = p4[j * 2];
        float4 q = p4[j * 2 + 1];
        as.x += s.x; as.y += s.y; as.z += s.z; as.w += s.w;
        aq.x += q.x; aq.y += q.y; aq.z += q.z; aq.w += q.w;
    }
    float r[8] = {as.x, as.y, as.z, as.w, aq.x, aq.y, aq.z, aq.w};
#pragma unroll
    for (int k = 0; k < 8; k++) {
#pragma unroll
        for (int off = 16; off; off >>= 1)
            r[k] += __shfl_down_sync(0xffffffffu, r[k], off);
    }
    if (lane == 0) {
#pragma unroll
        for (int k = 0; k < 8; k++) swarp[wrp][k] = r[k];
    }
    __syncthreads();

    if (tid < 4) {
        float s = 0.f, q = 0.f;
#pragma unroll
        for (int w = 0; w < 8; w++) { s += swarp[w][tid]; q += swarp[w][4 + tid]; }
        const float mean = s * (1.f / (float)B_TOTAL);
        const float ex2  = q * (1.f / (float)B_TOTAL);
        const float var  = fmaxf(ex2 - mean * mean, 0.f);
        const float inv  = rsqrtf(var + 1e-5f);
        const float sc   = gamma[tid] * inv;
        sb[tid]     = sc;
        sb[4 + tid] = beta[tid] - mean * sc;
    }
    __syncthreads();

    const float4 scv = *(const float4*)&sb[0];
    const float4 biv = *(const float4*)&sb[4];

    // normalize: 65536 float4 total / 128 blocks = 512 per block, 2 per thread
    float4* o4 = (float4*)out;
    int i = blockIdx.x * 512 + tid;
#pragma unroll
    for (int rep = 0; rep < 2; rep++, i += 256) {
        float4 v = o4[i];
        v.x = v.x * scv.x + biv.x;
        v.y = v.y * scv.y + biv.y;
        v.z = v.z * scv.z + biv.z;
        v.w = v.w * scv.w + biv.w;
        o4[i] = v;
    }
}

extern "C" void kernel_launch(void* const* d_in, const int* in_sizes, int n_in,
                              void* d_out, int out_size)
{
    const float* x      = (const float*)d_in[0];   // [65536,1,24,24]
    const float* params = (const float*)d_in[1];   // [4,2]
    const float* gamma  = (const float*)d_in[2];   // [4]
    const float* beta   = (const float*)d_in[3];   // [4]
    float* out = (float*)d_out;                    // [65536,4]

    qfc_kernelA<<<NB, THREADS>>>(x, params, out);
    qfc_kernelBC<<<NBC, 256>>>(gamma, beta, out);
}